// round 2
// baseline (speedup 1.0000x reference)
#include <cuda_runtime.h>
#include <math.h>

// Problem constants
#define TSTEPS 128
#define BATCH  1024
#define INDIM  47
#define HID    646
#define OUTDIM 5

// GEMM tiling: 64x64 tile, 64 threads, 8x8 microtile, packed f32x2 FMA
#define MTILE 64
#define NTILE 64
#define KTILE 16
#define TPB   64

#define MT (BATCH / MTILE)                 // 16
#define NT ((HID + NTILE - 1) / NTILE)     // 11
#define TILES (MT * NT)                    // 176
#define SZ (BATCH * HID)                   // 661504

typedef unsigned long long ull;

// Double-buffered recurrent state (device globals: no allocation allowed)
__device__ float g_h0[2][SZ];
__device__ float g_h1[2][SZ];

struct Job {
    const float* A1; int K1;   // first input segment  (x or h0)
    const float* A2; int K2;   // second input segment (recurrent h)
    const float* W1;           // [HID, K1] row-major
    const float* W2;           // [HID, K2] row-major
    const float* b1;
    const float* b2;
    float* C;                  // [BATCH, HID] output
};

__global__ void init_kernel() {
    int i = blockIdx.x * blockDim.x + threadIdx.x;
    if (i < SZ) {
        g_h0[1][i] = 0.0f;
        g_h1[1][i] = 0.0f;
    }
}

// ---- packed fp32x2 helpers (Blackwell FFMA2 path; full fp32 precision) ----
__device__ __forceinline__ ull pack2(float x) {
    ull r; asm("mov.b64 %0, {%1, %1};" : "=l"(r) : "f"(x)); return r;
}
__device__ __forceinline__ void fma2(ull& acc, ull a, ull b) {
    asm("fma.rn.f32x2 %0, %1, %2, %0;" : "+l"(acc) : "l"(a), "l"(b));
}
__device__ __forceinline__ float2 unpack2(ull v) {
    float lo, hi; asm("mov.b64 {%0, %1}, %2;" : "=f"(lo), "=f"(hi) : "l"(v));
    return make_float2(lo, hi);
}

// Accumulate C_tile += A[m0:m0+64, :K] * W[n0:n0+64, :K]^T  (both K-contiguous)
// Smem tiles are [KTILE][68] — stride 68 keeps 16B alignment for the float4 /
// ulonglong2 reads and the transposed scalar stores are conflict-free (lane = row).
// Each thread owns an 8(m) x 8(n) microtile => 64 FMAs per 64B of LDS (1 B/FMA).
__device__ __forceinline__ void gemm_accum(
    const float* __restrict__ A, const float* __restrict__ W, int K,
    int m0, int n0, ull acc[8][4],
    float* __restrict__ As, float* __restrict__ Bs, int tid)
{
    const float* Arow = A + (size_t)(m0 + tid) * K;
    const bool wv = (n0 + tid) < HID;
    const float* Wrow = W + (size_t)(wv ? (n0 + tid) : 0) * K;
    const int mgo = (tid & 7) << 3;     // row group offset within tile
    const int ngo = (tid >> 3) << 3;    // col group offset within tile

    float ra[KTILE], rb[KTILE];
    // prefetch first k-tile into registers
    #pragma unroll
    for (int i = 0; i < KTILE; i++) {
        ra[i] = (i < K) ? Arow[i] : 0.0f;
        rb[i] = (i < K && wv) ? Wrow[i] : 0.0f;
    }

    for (int k0 = 0; k0 < K; k0 += KTILE) {
        #pragma unroll
        for (int i = 0; i < KTILE; i++) {
            As[i * 68 + tid] = ra[i];
            Bs[i * 68 + tid] = rb[i];
        }
        __syncthreads();

        // prefetch next k-tile (overlaps with FMA block below)
        const int kn = k0 + KTILE;
        if (kn < K) {
            #pragma unroll
            for (int i = 0; i < KTILE; i++) {
                int k = kn + i;
                ra[i] = (k < K) ? Arow[k] : 0.0f;
                rb[i] = (k < K && wv) ? Wrow[k] : 0.0f;
            }
        }

        #pragma unroll
        for (int kk = 0; kk < KTILE; kk++) {
            const float* as = As + kk * 68 + mgo;
            const float* bs = Bs + kk * 68 + ngo;
            float4 a0 = *(const float4*)(as);
            float4 a1 = *(const float4*)(as + 4);
            ulonglong2 bb0 = *(const ulonglong2*)(bs);      // {b0b1, b2b3}
            ulonglong2 bb1 = *(const ulonglong2*)(bs + 4);  // {b4b5, b6b7}
            ull bv[4] = { bb0.x, bb0.y, bb1.x, bb1.y };
            ull av[8] = { pack2(a0.x), pack2(a0.y), pack2(a0.z), pack2(a0.w),
                          pack2(a1.x), pack2(a1.y), pack2(a1.z), pack2(a1.w) };
            #pragma unroll
            for (int i = 0; i < 8; i++) {
                #pragma unroll
                for (int j = 0; j < 4; j++) {
                    fma2(acc[i][j], av[i], bv[j]);
                }
            }
        }
        __syncthreads();
    }
}

// One fused launch: job0 (tiles [0,176)) and job1 (tiles [176,352)).
// Each job computes C = tanh(A1 @ W1^T + b1 + A2 @ W2^T + b2).
__global__ __launch_bounds__(TPB) void cell_kernel(Job j0, Job j1) {
    __shared__ float As[KTILE * 68];
    __shared__ float Bs[KTILE * 68];

    const int bid = blockIdx.x;
    const Job jb = (bid < TILES) ? j0 : j1;
    const int tile = (bid < TILES) ? bid : (bid - TILES);
    const int m0 = (tile / NT) * MTILE;
    const int n0 = (tile % NT) * NTILE;
    const int tid = threadIdx.x;

    ull acc[8][4] = {};   // 8 rows x 4 f32x2 (8 cols), zero-init == {0.f,0.f}
    gemm_accum(jb.A1, jb.W1, jb.K1, m0, n0, acc, As, Bs, tid);
    gemm_accum(jb.A2, jb.W2, jb.K2, m0, n0, acc, As, Bs, tid);

    const int mgo = (tid & 7) << 3;
    const int ngo = (tid >> 3) << 3;
    #pragma unroll
    for (int j = 0; j < 4; j++) {
        const int c0 = n0 + ngo + 2 * j;
        const int c1 = c0 + 1;
        const float blo = (c0 < HID) ? jb.b1[c0] + jb.b2[c0] : 0.0f;
        const float bhi = (c1 < HID) ? jb.b1[c1] + jb.b2[c1] : 0.0f;
        #pragma unroll
        for (int i = 0; i < 8; i++) {
            float2 v = unpack2(acc[i][j]);
            const size_t row = (size_t)(m0 + mgo + i) * HID;
            if (c0 < HID) jb.C[row + c0] = tanhf(v.x + blo);
            if (c1 < HID) jb.C[row + c1] = tanhf(v.y + bhi);
        }
    }
}

// logits[b,o] = h1[b,:] . Wout[o,:] + bout[o] ; one warp per (b,o)
__global__ void classifier_kernel(const float* __restrict__ h,
                                  const float* __restrict__ Wout,
                                  const float* __restrict__ bout,
                                  float* __restrict__ out) {
    int warp = (blockIdx.x * blockDim.x + threadIdx.x) >> 5;
    int lane = threadIdx.x & 31;
    if (warp >= BATCH * OUTDIM) return;
    int b = warp / OUTDIM, o = warp % OUTDIM;
    const float* hr = h + (size_t)b * HID;
    const float* wr = Wout + (size_t)o * HID;
    float s = 0.0f;
    for (int k = lane; k < HID; k += 32) s += hr[k] * wr[k];
    #pragma unroll
    for (int off = 16; off; off >>= 1) s += __shfl_down_sync(0xffffffff, s, off);
    if (lane == 0) out[b * OUTDIM + o] = s + bout[o];
}

extern "C" void kernel_launch(void* const* d_in, const int* in_sizes, int n_in,
                              void* d_out, int out_size) {
    const float* xs   = (const float*)d_in[0];
    const float* Wih0 = (const float*)d_in[1];
    const float* Whh0 = (const float*)d_in[2];
    const float* bih0 = (const float*)d_in[3];
    const float* bhh0 = (const float*)d_in[4];
    const float* Wih1 = (const float*)d_in[5];
    const float* Whh1 = (const float*)d_in[6];
    const float* bih1 = (const float*)d_in[7];
    const float* bhh1 = (const float*)d_in[8];
    const float* Wout = (const float*)d_in[9];
    const float* bout = (const float*)d_in[10];
    float* out = (float*)d_out;

    void* p;
    cudaGetSymbolAddress(&p, g_h0);
    float* h0b = (float*)p;              // h0b + parity*SZ
    cudaGetSymbolAddress(&p, g_h1);
    float* h1b = (float*)p;

    // zero the "t = -1" state slots (parity 1)
    init_kernel<<<(SZ + 255) / 256, 256>>>();

    // t = 0: layer0 only  h0(0) = f(x0, h0(-1)=0)
    {
        Job j0 = { xs, INDIM, h0b + SZ, HID, Wih0, Whh0, bih0, bhh0, h0b };
        cell_kernel<<<TILES, TPB>>>(j0, j0);
    }

    // t = 1..127: fused  h0(t) = f(x_t, h0(t-1))  ||  h1(t-1) = g(h0(t-1), h1(t-2))
    for (int t = 1; t < TSTEPS; t++) {
        const float* h0_prev = h0b + (size_t)((t - 1) & 1) * SZ;
        Job j0 = { xs + (size_t)t * BATCH * INDIM, INDIM,
                   h0_prev, HID,
                   Wih0, Whh0, bih0, bhh0,
                   h0b + (size_t)(t & 1) * SZ };
        Job j1 = { h0_prev, HID,
                   h1b + (size_t)(t & 1) * SZ,      // h1(t-2) lives at parity t%2
                   HID,
                   Wih1, Whh1, bih1, bhh1,
                   h1b + (size_t)((t - 1) & 1) * SZ };
        cell_kernel<<<2 * TILES, TPB>>>(j0, j1);
    }

    // drain: h1(127) = g(h0(127), h1(126))
    {
        Job jf = { h0b + SZ /* h0(127), parity 1 */, HID,
                   h1b /* h1(126), parity 0 */, HID,
                   Wih1, Whh1, bih1, bhh1,
                   h1b + SZ /* h1(127), parity 1 */ };
        cell_kernel<<<TILES, TPB>>>(jf, jf);
    }

    // classifier on h1(127)
    classifier_kernel<<<(BATCH * OUTDIM * 32 + 255) / 256, 256>>>(h1b + SZ, Wout, bout, out);
}

// round 3
// speedup vs baseline: 1.5610x; 1.5610x over previous
#include <cuda_runtime.h>
#include <math.h>

// Problem constants
#define TSTEPS 128
#define BATCH  1024
#define INDIM  47
#define HID    646
#define OUTDIM 5

// GEMM tiling: 64x64 tile, 256 threads, 4x4 microtile, packed f32x2 FMA
#define MTILE 64
#define NTILE 64
#define KTILE 16
#define TPB   256
#define GRID  296              // 2 CTAs / SM, persistent-ish with work stealing

#define MT (BATCH / MTILE)                 // 16
#define NT ((HID + NTILE - 1) / NTILE)     // 11
#define TILES (MT * NT)                    // 176
#define SZ (BATCH * HID)                   // 661504

typedef unsigned long long ull;

// Double-buffered recurrent state + per-launch work counters (no allocation allowed)
__device__ float g_h0[2][SZ];
__device__ float g_h1[2][SZ];
__device__ unsigned int g_counter[TSTEPS + 2];

struct Job {
    const float* A1; int K1;   // first input segment  (x or h0)
    const float* A2; int K2;   // second input segment (recurrent h)
    const float* W1;           // [HID, K1] row-major
    const float* W2;           // [HID, K2] row-major
    const float* b1;
    const float* b2;
    float* C;                  // [BATCH, HID] output
};

__global__ void init_kernel() {
    int i = blockIdx.x * blockDim.x + threadIdx.x;
    if (i < SZ) {
        g_h0[1][i] = 0.0f;
        g_h1[1][i] = 0.0f;
    }
    if (i < TSTEPS + 2) g_counter[i] = 0u;
}

// ---- packed fp32x2 helpers (Blackwell FFMA2 path; full fp32 precision) ----
__device__ __forceinline__ ull pack2(float x) {
    ull r; asm("mov.b64 %0, {%1, %1};" : "=l"(r) : "f"(x)); return r;
}
__device__ __forceinline__ void fma2(ull& acc, ull a, ull b) {
    asm("fma.rn.f32x2 %0, %1, %2, %0;" : "+l"(acc) : "l"(a), "l"(b));
}
__device__ __forceinline__ float2 unpack2(ull v) {
    float lo, hi; asm("mov.b64 {%0, %1}, %2;" : "=f"(lo), "=f"(hi) : "l"(v));
    return make_float2(lo, hi);
}

// Accumulate C_tile += A[m0:m0+64, :K] * W[n0:n0+64, :K]^T  (both K-contiguous).
// Smem tiles are [2][KTILE][68]: stride 68 keeps 16B alignment for the vector
// reads; double-buffered so there is ONE __syncthreads per k-tile.
// acc[i][j] is an f32x2 pair over columns (ngo+2j, ngo+2j+1) for row mgo+i.
__device__ __forceinline__ void gemm_accum(
    const float* __restrict__ A, const float* __restrict__ W, int K,
    int m0, int n0, ull acc[4][2],
    float (*__restrict__ As)[KTILE * 68], float (*__restrict__ Bs)[KTILE * 68],
    int tid)
{
    const int lrow = tid >> 2;          // 0..63 : tile row (m for A, n for W)
    const int lk4  = (tid & 3) << 2;    // 0,4,8,12 : k offset group
    const int mgo  = (tid & 15) << 2;   // micro-tile m offset
    const int ngo  = (tid >> 4) << 2;   // micro-tile n offset

    const float* Arow = A + (size_t)(m0 + lrow) * K;
    const bool wv = (n0 + lrow) < HID;
    const float* Wrow = W + (size_t)(wv ? (n0 + lrow) : 0) * K;

    const int nk = (K + KTILE - 1) / KTILE;

    float ra[4], rb[4];
    #pragma unroll
    for (int i = 0; i < 4; i++) {
        int k = lk4 + i;
        ra[i] = (k < K) ? Arow[k] : 0.0f;
        rb[i] = (k < K && wv) ? Wrow[k] : 0.0f;
    }
    #pragma unroll
    for (int i = 0; i < 4; i++) {
        As[0][(lk4 + i) * 68 + lrow] = ra[i];
        Bs[0][(lk4 + i) * 68 + lrow] = rb[i];
    }
    __syncthreads();

    for (int kt = 0; kt < nk; kt++) {
        const int kn = (kt + 1) * KTILE;
        if (kt + 1 < nk) {
            #pragma unroll
            for (int i = 0; i < 4; i++) {
                int k = kn + lk4 + i;
                ra[i] = (k < K) ? Arow[k] : 0.0f;
                rb[i] = (k < K && wv) ? Wrow[k] : 0.0f;
            }
        }

        const float* as = As[kt & 1];
        const float* bs = Bs[kt & 1];
        #pragma unroll
        for (int kk = 0; kk < KTILE; kk++) {
            float4 a = *(const float4*)(as + kk * 68 + mgo);
            ulonglong2 b = *(const ulonglong2*)(bs + kk * 68 + ngo);
            ull a0 = pack2(a.x), a1 = pack2(a.y), a2 = pack2(a.z), a3 = pack2(a.w);
            fma2(acc[0][0], a0, b.x); fma2(acc[0][1], a0, b.y);
            fma2(acc[1][0], a1, b.x); fma2(acc[1][1], a1, b.y);
            fma2(acc[2][0], a2, b.x); fma2(acc[2][1], a2, b.y);
            fma2(acc[3][0], a3, b.x); fma2(acc[3][1], a3, b.y);
        }

        if (kt + 1 < nk) {
            const int nb = (kt + 1) & 1;
            #pragma unroll
            for (int i = 0; i < 4; i++) {
                As[nb][(lk4 + i) * 68 + lrow] = ra[i];
                Bs[nb][(lk4 + i) * 68 + lrow] = rb[i];
            }
        }
        __syncthreads();
    }
}

// Work-stealing cell kernel. Tile indices [0, TILES) -> jH (heavy, dispatched
// first); [TILES, ntiles) -> jL. Each tile: C = tanh(A1@W1^T + b1 + A2@W2^T + b2).
__global__ __launch_bounds__(TPB) void cell_kernel(Job jH, Job jL,
                                                   int cidx, int ntiles) {
    __shared__ float As[2][KTILE * 68];
    __shared__ float Bs[2][KTILE * 68];
    __shared__ unsigned int s_idx;

    const int tid = threadIdx.x;

    for (;;) {
        if (tid == 0) s_idx = atomicAdd(&g_counter[cidx], 1u);
        __syncthreads();
        const unsigned int idx = s_idx;
        if (idx >= (unsigned int)ntiles) break;

        const Job jb = (idx < TILES) ? jH : jL;
        const int tile = (idx < TILES) ? (int)idx : (int)idx - TILES;
        const int m0 = (tile / NT) * MTILE;
        const int n0 = (tile % NT) * NTILE;

        ull acc[4][2] = {};   // zero bits == {0.f, 0.f}
        gemm_accum(jb.A1, jb.W1, jb.K1, m0, n0, acc, As, Bs, tid);
        gemm_accum(jb.A2, jb.W2, jb.K2, m0, n0, acc, As, Bs, tid);

        const int mgo = (tid & 15) << 2;
        const int ngo = (tid >> 4) << 2;
        #pragma unroll
        for (int j = 0; j < 2; j++) {
            const int c0 = n0 + ngo + 2 * j;
            if (c0 < HID) {   // HID even, c0 even -> pair fully valid
                const float blo = jb.b1[c0] + jb.b2[c0];
                const float bhi = jb.b1[c0 + 1] + jb.b2[c0 + 1];
                #pragma unroll
                for (int i = 0; i < 4; i++) {
                    float2 v = unpack2(acc[i][j]);
                    float2 o = make_float2(tanhf(v.x + blo), tanhf(v.y + bhi));
                    *(float2*)(jb.C + (size_t)(m0 + mgo + i) * HID + c0) = o;
                }
            }
        }
        // gemm_accum ends with __syncthreads(); epilogue touches no smem,
        // and the loop-top sync guards the s_idx handoff.
    }
}

// logits[b,o] = h1[b,:] . Wout[o,:] + bout[o] ; one warp per (b,o)
__global__ void classifier_kernel(const float* __restrict__ h,
                                  const float* __restrict__ Wout,
                                  const float* __restrict__ bout,
                                  float* __restrict__ out) {
    int warp = (blockIdx.x * blockDim.x + threadIdx.x) >> 5;
    int lane = threadIdx.x & 31;
    if (warp >= BATCH * OUTDIM) return;
    int b = warp / OUTDIM, o = warp % OUTDIM;
    const float* hr = h + (size_t)b * HID;
    const float* wr = Wout + (size_t)o * HID;
    float s = 0.0f;
    for (int k = lane; k < HID; k += 32) s += hr[k] * wr[k];
    #pragma unroll
    for (int off = 16; off; off >>= 1) s += __shfl_down_sync(0xffffffff, s, off);
    if (lane == 0) out[b * OUTDIM + o] = s + bout[o];
}

extern "C" void kernel_launch(void* const* d_in, const int* in_sizes, int n_in,
                              void* d_out, int out_size) {
    const float* xs   = (const float*)d_in[0];
    const float* Wih0 = (const float*)d_in[1];
    const float* Whh0 = (const float*)d_in[2];
    const float* bih0 = (const float*)d_in[3];
    const float* bhh0 = (const float*)d_in[4];
    const float* Wih1 = (const float*)d_in[5];
    const float* Whh1 = (const float*)d_in[6];
    const float* bih1 = (const float*)d_in[7];
    const float* bhh1 = (const float*)d_in[8];
    const float* Wout = (const float*)d_in[9];
    const float* bout = (const float*)d_in[10];
    float* out = (float*)d_out;

    void* p;
    cudaGetSymbolAddress(&p, g_h0);
    float* h0b = (float*)p;              // h0b + parity*SZ
    cudaGetSymbolAddress(&p, g_h1);
    float* h1b = (float*)p;

    // zero the "t = -1" state slots (parity 1) and all work counters
    init_kernel<<<(SZ + 255) / 256, 256>>>();

    // t = 0: layer0 only  h0(0) = f(x0, h0(-1)=0)
    {
        Job j0 = { xs, INDIM, h0b + SZ, HID, Wih0, Whh0, bih0, bhh0, h0b };
        cell_kernel<<<GRID, TPB>>>(j0, j0, 0, TILES);
    }

    // t = 1..127: fused  h0(t) = f(x_t, h0(t-1))  ||  h1(t-1) = g(h0(t-1), h1(t-2))
    for (int t = 1; t < TSTEPS; t++) {
        const float* h0_prev = h0b + (size_t)((t - 1) & 1) * SZ;
        Job j0 = { xs + (size_t)t * BATCH * INDIM, INDIM,
                   h0_prev, HID,
                   Wih0, Whh0, bih0, bhh0,
                   h0b + (size_t)(t & 1) * SZ };
        Job j1 = { h0_prev, HID,
                   h1b + (size_t)(t & 1) * SZ,      // h1(t-2) lives at parity t%2
                   HID,
                   Wih1, Whh1, bih1, bhh1,
                   h1b + (size_t)((t - 1) & 1) * SZ };
        // heavy job (K=1292) dispatched first, light tail
        cell_kernel<<<GRID, TPB>>>(j1, j0, t, 2 * TILES);
    }

    // drain: h1(127) = g(h0(127), h1(126))
    {
        Job jf = { h0b + SZ /* h0(127), parity 1 */, HID,
                   h1b /* h1(126), parity 0 */, HID,
                   Wih1, Whh1, bih1, bhh1,
                   h1b + SZ /* h1(127), parity 1 */ };
        cell_kernel<<<GRID, TPB>>>(jf, jf, TSTEPS, TILES);
    }

    // classifier on h1(127)
    classifier_kernel<<<(BATCH * OUTDIM * 32 + 255) / 256, 256>>>(h1b + SZ, Wout, bout, out);
}